// round 9
// baseline (speedup 1.0000x reference)
#include <cuda_runtime.h>
#include <cuda_bf16.h>
#include <math.h>
#include <cstdint>

#define MAXN    6144
#define D       512
#define D4      128
#define INV_PI  0.318309886183790671f

// ---------------- device scratch (allocation-free rule) ----------------
__device__ int   g_prev[MAXN];
__device__ int   g_next[MAXN];
__device__ float g_wprev[MAXN];
// gathered X split: [MAXN][1024 bf16] = (hi | lo), row stride 2048 B
// rows >= N never written -> stay zero from static init
__device__ unsigned char g_ahl[MAXN * 2048];
// W split: [512][1536 bf16] = (hi | lo | hi), row stride 3072 B
__device__ unsigned char g_bhl[512 * 3072];

__device__ __forceinline__ uint32_t smem_u32(const void* p) {
    uint32_t a;
    asm("{ .reg .u64 t; cvta.to.shared.u64 t, %1; cvt.u32.u64 %0, t; }"
        : "=r"(a) : "l"(p));
    return a;
}

#define LDM4(r, addr) \
    asm volatile("ldmatrix.sync.aligned.m8n8.x4.shared.b16 {%0,%1,%2,%3}, [%4];" \
        : "=r"((r)[0]), "=r"((r)[1]), "=r"((r)[2]), "=r"((r)[3]) : "r"(addr))

#define MMA16816(c, a, b0, b1) \
    asm volatile("mma.sync.aligned.m16n8k16.row.col.f32.bf16.bf16.f32 " \
        "{%0,%1,%2,%3}, {%4,%5,%6,%7}, {%8,%9}, {%0,%1,%2,%3};" \
        : "+f"((c)[0]), "+f"((c)[1]), "+f"((c)[2]), "+f"((c)[3]) \
        : "r"((a)[0]), "r"((a)[1]), "r"((a)[2]), "r"((a)[3]), "r"(b0), "r"(b1))

#define CP16(dst, src) \
    asm volatile("cp.async.cg.shared.global [%0], [%1], 16;" :: "r"(dst), "l"(src))
#define CP_COMMIT() asm volatile("cp.async.commit_group;" ::: "memory")
#define CP_WAIT0()  asm volatile("cp.async.wait_group 0;" ::: "memory")

// ---------------------------------------------------------------------------
// Kernel 1: per-dialog prev/next chains, parallel backward/forward smem scan.
// ---------------------------------------------------------------------------
__global__ __launch_bounds__(128)
void prep_kernel(const int* __restrict__ dl,
                 const int* __restrict__ q,
                 int n_dialogs, int N)
{
    __shared__ int s_dl[512];
    __shared__ int s_sp[512];
    __shared__ int s_q64;

    int d = blockIdx.x;
    if (d >= n_dialogs) return;
    int tid = threadIdx.x;

    if (tid == 0) s_q64 = 0;
    __syncthreads();
    if (tid < 64 && tid < N) {
        if (q[2 * tid] + q[2 * tid + 1] != 1) atomicExch(&s_q64, 1);
    }
    int dstride = (dl[1] == 0) ? 2 : 1;
    for (int t = tid; t < n_dialogs && t < 512; t += blockDim.x)
        s_dl[t] = dl[t * dstride];
    __syncthreads();
    int qstride = s_q64 ? 4 : 2;

    int start = 0;
    for (int t = 0; t < d; ++t) start += s_dl[t];
    int len = s_dl[d];

    for (int t = tid; t < len; t += blockDim.x)
        s_sp[t] = (q[(size_t)(start + t) * qstride] == 1) ? 0 : 1;
    __syncthreads();

    for (int t = tid; t < len; t += blockDim.x) {
        int s = s_sp[t];
        int pv = -1, nx = -1;
        for (int j = t - 1; j >= 0; --j)
            if (s_sp[j] == s) { pv = start + j; break; }
        for (int j = t + 1; j < len; ++j)
            if (s_sp[j] == s) { nx = start + j; break; }
        g_prev[start + t] = pv;
        g_next[start + t] = nx;
    }
}

// ---------------------------------------------------------------------------
// Kernel 2: edge weights, one warp per node.
// ---------------------------------------------------------------------------
__global__ void wt_kernel(const float* __restrict__ inputs, int N)
{
    int i = blockIdx.x * 8 + (threadIdx.x >> 5);
    if (i >= N) return;
    int p = g_prev[i];
    if (p < 0) return;
    int lane = threadIdx.x & 31;

    const float4* a4 = (const float4*)(inputs + (size_t)i * D);
    const float4* b4 = (const float4*)(inputs + (size_t)p * D);
    float dot = 0.f, na = 0.f, nb = 0.f;
    #pragma unroll
    for (int j = lane; j < D4; j += 32) {
        float4 a = a4[j];
        float4 b = b4[j];
        dot += a.x * b.x + a.y * b.y + a.z * b.z + a.w * b.w;
        na  += a.x * a.x + a.y * a.y + a.z * a.z + a.w * a.w;
        nb  += b.x * b.x + b.y * b.y + b.z * b.z + b.w * b.w;
    }
    #pragma unroll
    for (int off = 16; off > 0; off >>= 1) {
        dot += __shfl_down_sync(0xffffffffu, dot, off);
        na  += __shfl_down_sync(0xffffffffu, na,  off);
        nb  += __shfl_down_sync(0xffffffffu, nb,  off);
    }
    if (lane == 0) {
        float denom = sqrtf(na) * sqrtf(nb);
        float c = (denom > 0.f) ? (dot / denom) : 0.f;
        c = fminf(1.f, fmaxf(-1.f, c));
        g_wprev[i] = 1.f - acosf(c) * INV_PI;
    }
}

// ---------------------------------------------------------------------------
// Kernel 3: fused gather + bf16 hi/lo split (X) and W split.
// ---------------------------------------------------------------------------
__global__ void split_kernel(const float* __restrict__ inputs,
                             const float* __restrict__ Wm, int N)
{
    int b = blockIdx.x;
    int t = threadIdx.x;
    float f[4];

    if (b < N) {
        const float4* in4 = (const float4*)inputs;
        float4 v = in4[(size_t)b * D4 + t];
        int p  = g_prev[b];
        int nx = g_next[b];
        if (p >= 0) {
            float w = g_wprev[b];
            float4 u = in4[(size_t)p * D4 + t];
            v.x += w * u.x; v.y += w * u.y; v.z += w * u.z; v.w += w * u.w;
        }
        if (nx >= 0) {
            float w = g_wprev[nx];
            float4 u = in4[(size_t)nx * D4 + t];
            v.x += w * u.x; v.y += w * u.y; v.z += w * u.z; v.w += w * u.w;
        }
        f[0] = v.x; f[1] = v.y; f[2] = v.z; f[3] = v.w;
    } else {
        int r = b - N;
        float4 w = ((const float4*)(Wm + (size_t)r * D))[t];
        f[0] = w.x; f[1] = w.y; f[2] = w.z; f[3] = w.w;
    }

    unsigned short hs[4], ls[4];
    #pragma unroll
    for (int j = 0; j < 4; ++j) {
        __nv_bfloat16 h = __float2bfloat16(f[j]);
        __nv_bfloat16 l = __float2bfloat16(f[j] - __bfloat162float(h));
        hs[j] = __bfloat16_as_ushort(h);
        ls[j] = __bfloat16_as_ushort(l);
    }
    uint2 hv = make_uint2((uint32_t)hs[0] | ((uint32_t)hs[1] << 16),
                          (uint32_t)hs[2] | ((uint32_t)hs[3] << 16));
    uint2 lv = make_uint2((uint32_t)ls[0] | ((uint32_t)ls[1] << 16),
                          (uint32_t)ls[2] | ((uint32_t)ls[3] << 16));

    if (b < N) {
        unsigned char* row = g_ahl + (size_t)b * 2048;
        ((uint2*)row)[t]          = hv;
        ((uint2*)(row + 1024))[t] = lv;
    } else {
        unsigned char* row = g_bhl + (size_t)(b - N) * 3072;
        ((uint2*)row)[t]          = hv;
        ((uint2*)(row + 1024))[t] = lv;
        ((uint2*)(row + 2048))[t] = hv;
    }
}

// ---------------------------------------------------------------------------
// Kernel 4: HMMA GEMM  out[N,512] = Acat x Bcat^T + bias  (fp32 accum)
// Block 128x128, BK=32, 256 threads = 8 warps of 64x32 warp tiles.
// cp.async double-buffered, 80B-padded rows, grid 47x4 = 188 CTAs (1 wave).
// ---------------------------------------------------------------------------
__global__ __launch_bounds__(256, 2)
void gemm_mma(const float* __restrict__ bias, float* __restrict__ out, int N)
{
    __shared__ __align__(16) unsigned char sA[2][128 * 80];
    __shared__ __align__(16) unsigned char sB[2][128 * 80];

    int t = threadIdx.x;
    int m0 = blockIdx.x * 128;
    int n0 = blockIdx.y * 128;
    int lane = t & 31, w = t >> 5;
    int wm = w >> 2;           // 0..1  -> 64-row group
    int wn = w & 3;            // 0..3  -> 32-col group

    // ---- staging: A rows m0+sr, m0+sr+64; B rows n0+sr, n0+sr+64 ----
    int sr = t >> 2, sc = t & 3;
    const unsigned char* gA0 = g_ahl + (size_t)(m0 + sr)      * 2048 + sc * 16;
    const unsigned char* gA1 = g_ahl + (size_t)(m0 + sr + 64) * 2048 + sc * 16;
    const unsigned char* gB0 = g_bhl + (size_t)(n0 + sr)      * 3072 + sc * 16;
    const unsigned char* gB1 = g_bhl + (size_t)(n0 + sr + 64) * 3072 + sc * 16;

    uint32_t sa[2] = { smem_u32(sA[0]), smem_u32(sA[1]) };
    uint32_t sb[2] = { smem_u32(sB[0]), smem_u32(sB[1]) };
    uint32_t st0 = sr * 80 + sc * 16;
    uint32_t st1 = (sr + 64) * 80 + sc * 16;

    uint32_t a_ld = (uint32_t)(wm * 64 + (lane & 15)) * 80 + ((lane >> 4) * 16);
    uint32_t b_ld = (uint32_t)(wn * 32 + (lane & 15)) * 80 + ((lane >> 4) * 16);

    float acc[4][4][4];
    #pragma unroll
    for (int i = 0; i < 4; ++i)
        #pragma unroll
        for (int j = 0; j < 4; ++j)
            #pragma unroll
            for (int r = 0; r < 4; ++r) acc[i][j][r] = 0.f;

    auto issue = [&](int it, int buf) {
        int k = it * 32;
        int aoff = (k >= 512 ? k - 512 : k) * 2;   // hi|hi|lo via contiguity
        int boff = k * 2;                          // hi|lo|hi directly
        CP16(sa[buf] + st0, gA0 + aoff);
        CP16(sa[buf] + st1, gA1 + aoff);
        CP16(sb[buf] + st0, gB0 + boff);
        CP16(sb[buf] + st1, gB1 + boff);
        CP_COMMIT();
    };

    issue(0, 0);

    #pragma unroll 1
    for (int it = 0; it < 48; ++it) {
        int buf = it & 1;
        CP_WAIT0();
        __syncthreads();
        if (it < 47) issue(it + 1, buf ^ 1);

        uint32_t ab = sa[buf] + a_ld;
        uint32_t bb = sb[buf] + b_ld;
        #pragma unroll
        for (int kk = 0; kk < 2; ++kk) {
            uint32_t A[4][4], B0[4], B1[4];
            #pragma unroll
            for (int mi = 0; mi < 4; ++mi)
                LDM4(A[mi], ab + mi * (16 * 80) + kk * 32);
            LDM4(B0, bb + kk * 32);
            LDM4(B1, bb + 16 * 80 + kk * 32);
            #pragma unroll
            for (int mi = 0; mi < 4; ++mi) {
                MMA16816(acc[mi][0], A[mi], B0[0], B0[2]);
                MMA16816(acc[mi][1], A[mi], B0[1], B0[3]);
                MMA16816(acc[mi][2], A[mi], B1[0], B1[2]);
                MMA16816(acc[mi][3], A[mi], B1[1], B1[3]);
            }
        }
    }

    // ---- epilogue: add bias, store out ----
    int r0 = m0 + wm * 64 + (lane >> 2);
    int cb = n0 + wn * 32 + (lane & 3) * 2;
    #pragma unroll
    for (int mi = 0; mi < 4; ++mi) {
        int row = r0 + mi * 16;
        #pragma unroll
        for (int nj = 0; nj < 4; ++nj) {
            int col = cb + nj * 8;
            float b0 = __ldg(bias + col);
            float b1 = __ldg(bias + col + 1);
            if (row < N)
                *(float2*)(out + (size_t)row * D + col) =
                    make_float2(acc[mi][nj][0] + b0, acc[mi][nj][1] + b1);
            if (row + 8 < N)
                *(float2*)(out + (size_t)(row + 8) * D + col) =
                    make_float2(acc[mi][nj][2] + b0, acc[mi][nj][3] + b1);
        }
    }
}

// ---------------------------------------------------------------------------
extern "C" void kernel_launch(void* const* d_in, const int* in_sizes, int n_in,
                              void* d_out, int out_size)
{
    const float* inputs  = (const float*)d_in[0];
    const int*   dia_len = (const int*)d_in[1];
    const int*   qmask   = (const int*)d_in[2];
    const float* Wm      = (const float*)d_in[3];
    const float* bias    = (const float*)d_in[4];
    float*       out     = (float*)d_out;

    int N  = in_sizes[0] / D;      // 6000
    int nd = in_sizes[1];
    if (nd > N) nd = N;

    prep_kernel<<<nd, 128>>>(dia_len, qmask, nd, N);
    wt_kernel<<<(N + 7) / 8, 256>>>(inputs, N);
    split_kernel<<<N + 512, 128>>>(inputs, Wm, N);

    dim3 grid((N + 127) / 128, D / 128);
    gemm_mma<<<grid, 256>>>(bias, out, N);
}

// round 10
// speedup vs baseline: 1.2931x; 1.2931x over previous
#include <cuda_runtime.h>
#include <cuda_bf16.h>
#include <math.h>
#include <cstdint>

#define MAXN    6144
#define D       512
#define D4      128
#define INV_PI  0.318309886183790671f

// smem: 2 stages x (128 A rows + 64 B rows) x 144B (128B data + 16B pad)
#define ROWPITCH 144
#define STAGE_BYTES ((128 + 64) * ROWPITCH)     // 27648
#define SMEM_TOTAL (2 * STAGE_BYTES)            // 55296
#define B_OFF (128 * ROWPITCH)                  // B region within a stage

// ---------------- device scratch (allocation-free rule) ----------------
__device__ int   g_prev[MAXN];
__device__ int   g_next[MAXN];
__device__ float g_wprev[MAXN];
// gathered X split: [MAXN][1024 bf16] = (hi | lo), row stride 2048 B
// rows >= N never written -> stay zero from static init
__device__ unsigned char g_ahl[MAXN * 2048];
// W split: [512][1536 bf16] = (hi | lo | hi), row stride 3072 B
__device__ unsigned char g_bhl[512 * 3072];

__device__ __forceinline__ uint32_t smem_u32(const void* p) {
    uint32_t a;
    asm("{ .reg .u64 t; cvta.to.shared.u64 t, %1; cvt.u32.u64 %0, t; }"
        : "=r"(a) : "l"(p));
    return a;
}

#define LDM4(r, addr) \
    asm volatile("ldmatrix.sync.aligned.m8n8.x4.shared.b16 {%0,%1,%2,%3}, [%4];" \
        : "=r"((r)[0]), "=r"((r)[1]), "=r"((r)[2]), "=r"((r)[3]) : "r"(addr))

#define MMA16816(c, a, b0, b1) \
    asm volatile("mma.sync.aligned.m16n8k16.row.col.f32.bf16.bf16.f32 " \
        "{%0,%1,%2,%3}, {%4,%5,%6,%7}, {%8,%9}, {%0,%1,%2,%3};" \
        : "+f"((c)[0]), "+f"((c)[1]), "+f"((c)[2]), "+f"((c)[3]) \
        : "r"((a)[0]), "r"((a)[1]), "r"((a)[2]), "r"((a)[3]), "r"(b0), "r"(b1))

#define CP16(dst, src) \
    asm volatile("cp.async.cg.shared.global [%0], [%1], 16;" :: "r"(dst), "l"(src))
#define CP_COMMIT() asm volatile("cp.async.commit_group;" ::: "memory")
#define CP_WAIT0()  asm volatile("cp.async.wait_group 0;" ::: "memory")

// ---------------------------------------------------------------------------
// Kernel 1: per-dialog prev/next chains, parallel smem scans.
// ---------------------------------------------------------------------------
__global__ __launch_bounds__(128)
void prep_kernel(const int* __restrict__ dl,
                 const int* __restrict__ q,
                 int n_dialogs, int N)
{
    __shared__ int s_dl[512];
    __shared__ int s_sp[512];
    __shared__ int s_q64;

    int d = blockIdx.x;
    if (d >= n_dialogs) return;
    int tid = threadIdx.x;

    if (tid == 0) s_q64 = 0;
    __syncthreads();
    if (tid < 64 && tid < N) {
        if (q[2 * tid] + q[2 * tid + 1] != 1) atomicExch(&s_q64, 1);
    }
    int dstride = (dl[1] == 0) ? 2 : 1;
    for (int t = tid; t < n_dialogs && t < 512; t += blockDim.x)
        s_dl[t] = dl[t * dstride];
    __syncthreads();
    int qstride = s_q64 ? 4 : 2;

    int start = 0;
    for (int t = 0; t < d; ++t) start += s_dl[t];
    int len = s_dl[d];

    for (int t = tid; t < len; t += blockDim.x)
        s_sp[t] = (q[(size_t)(start + t) * qstride] == 1) ? 0 : 1;
    __syncthreads();

    for (int t = tid; t < len; t += blockDim.x) {
        int s = s_sp[t];
        int pv = -1, nx = -1;
        for (int j = t - 1; j >= 0; --j)
            if (s_sp[j] == s) { pv = start + j; break; }
        for (int j = t + 1; j < len; ++j)
            if (s_sp[j] == s) { nx = start + j; break; }
        g_prev[start + t] = pv;
        g_next[start + t] = nx;
    }
}

// ---------------------------------------------------------------------------
// Kernel 2: edge weights, one warp per node.
// ---------------------------------------------------------------------------
__global__ void wt_kernel(const float* __restrict__ inputs, int N)
{
    int i = blockIdx.x * 8 + (threadIdx.x >> 5);
    if (i >= N) return;
    int p = g_prev[i];
    if (p < 0) return;
    int lane = threadIdx.x & 31;

    const float4* a4 = (const float4*)(inputs + (size_t)i * D);
    const float4* b4 = (const float4*)(inputs + (size_t)p * D);
    float dot = 0.f, na = 0.f, nb = 0.f;
    #pragma unroll
    for (int j = lane; j < D4; j += 32) {
        float4 a = a4[j];
        float4 b = b4[j];
        dot += a.x * b.x + a.y * b.y + a.z * b.z + a.w * b.w;
        na  += a.x * a.x + a.y * a.y + a.z * a.z + a.w * a.w;
        nb  += b.x * b.x + b.y * b.y + b.z * b.z + b.w * b.w;
    }
    #pragma unroll
    for (int off = 16; off > 0; off >>= 1) {
        dot += __shfl_down_sync(0xffffffffu, dot, off);
        na  += __shfl_down_sync(0xffffffffu, na,  off);
        nb  += __shfl_down_sync(0xffffffffu, nb,  off);
    }
    if (lane == 0) {
        float denom = sqrtf(na) * sqrtf(nb);
        float c = (denom > 0.f) ? (dot / denom) : 0.f;
        c = fminf(1.f, fmaxf(-1.f, c));
        g_wprev[i] = 1.f - acosf(c) * INV_PI;
    }
}

// ---------------------------------------------------------------------------
// Kernel 3: fused gather + bf16 hi/lo split (X) and W split.
// ---------------------------------------------------------------------------
__global__ void split_kernel(const float* __restrict__ inputs,
                             const float* __restrict__ Wm, int N)
{
    int b = blockIdx.x;
    int t = threadIdx.x;
    float f[4];

    if (b < N) {
        const float4* in4 = (const float4*)inputs;
        float4 v = in4[(size_t)b * D4 + t];
        int p  = g_prev[b];
        int nx = g_next[b];
        if (p >= 0) {
            float w = g_wprev[b];
            float4 u = in4[(size_t)p * D4 + t];
            v.x += w * u.x; v.y += w * u.y; v.z += w * u.z; v.w += w * u.w;
        }
        if (nx >= 0) {
            float w = g_wprev[nx];
            float4 u = in4[(size_t)nx * D4 + t];
            v.x += w * u.x; v.y += w * u.y; v.z += w * u.z; v.w += w * u.w;
        }
        f[0] = v.x; f[1] = v.y; f[2] = v.z; f[3] = v.w;
    } else {
        int r = b - N;
        float4 w = ((const float4*)(Wm + (size_t)r * D))[t];
        f[0] = w.x; f[1] = w.y; f[2] = w.z; f[3] = w.w;
    }

    unsigned short hs[4], ls[4];
    #pragma unroll
    for (int j = 0; j < 4; ++j) {
        __nv_bfloat16 h = __float2bfloat16(f[j]);
        __nv_bfloat16 l = __float2bfloat16(f[j] - __bfloat162float(h));
        hs[j] = __bfloat16_as_ushort(h);
        ls[j] = __bfloat16_as_ushort(l);
    }
    uint2 hv = make_uint2((uint32_t)hs[0] | ((uint32_t)hs[1] << 16),
                          (uint32_t)hs[2] | ((uint32_t)hs[3] << 16));
    uint2 lv = make_uint2((uint32_t)ls[0] | ((uint32_t)ls[1] << 16),
                          (uint32_t)ls[2] | ((uint32_t)ls[3] << 16));

    if (b < N) {
        unsigned char* row = g_ahl + (size_t)b * 2048;
        ((uint2*)row)[t]          = hv;
        ((uint2*)(row + 1024))[t] = lv;
    } else {
        unsigned char* row = g_bhl + (size_t)(b - N) * 3072;
        ((uint2*)row)[t]          = hv;
        ((uint2*)(row + 1024))[t] = lv;
        ((uint2*)(row + 2048))[t] = hv;
    }
}

// ---------------------------------------------------------------------------
// Kernel 4: HMMA GEMM  out[N,512] = Acat x Bcat^T + bias  (fp32 accum)
// Block 128x64, BK=64 (24 iters), 256 threads = 8 warps of 32x32 tiles,
// cp.async double-buffered dynamic smem (144B-pitch rows), grid 376 (1 wave).
// ---------------------------------------------------------------------------
__global__ __launch_bounds__(256, 3)
void gemm_mma(const float* __restrict__ bias, float* __restrict__ out, int N)
{
    extern __shared__ __align__(16) unsigned char smem[];

    int t = threadIdx.x;
    int m0 = blockIdx.x * 128;
    int n0 = blockIdx.y * 64;
    int lane = t & 31, w = t >> 5;
    int wm = w >> 1;           // 0..3 -> 32-row group
    int wn = w & 1;            // 0..1 -> 32-col group

    uint32_t sbase = smem_u32(smem);
    uint32_t stg[2] = { sbase, sbase + STAGE_BYTES };

    // ---- cp.async chunk mapping: A 1024 chunks (4/thread), B 512 (2/thread)
    int ar[4], ac[4], br[2], bc[2];
    #pragma unroll
    for (int j = 0; j < 4; ++j) {
        int c = t + j * 256;
        ar[j] = c >> 3; ac[j] = c & 7;
    }
    #pragma unroll
    for (int j = 0; j < 2; ++j) {
        int c = t + j * 256;
        br[j] = c >> 3; bc[j] = c & 7;
    }

    uint32_t a_ld = (uint32_t)(wm * 32 + (lane & 15)) * ROWPITCH + ((lane >> 4) * 16);
    uint32_t b_ld = (uint32_t)(B_OFF + (wn * 32 + (lane & 15)) * ROWPITCH) + ((lane >> 4) * 16);

    float acc[2][4][4];
    #pragma unroll
    for (int i = 0; i < 2; ++i)
        #pragma unroll
        for (int j = 0; j < 4; ++j)
            #pragma unroll
            for (int r = 0; r < 4; ++r) acc[i][j][r] = 0.f;

    // issue cp.async for K-chunk `it` (64 k-values) into stage `buf`
    auto issue = [&](int it, int buf) {
        int k0 = it * 64;
        int aoff = (k0 >= 512 ? k0 - 512 : k0) * 2;   // A: hi|hi|lo
        int boff = k0 * 2;                            // B: hi|lo|hi
        uint32_t s = stg[buf];
        #pragma unroll
        for (int j = 0; j < 4; ++j)
            CP16(s + ar[j] * ROWPITCH + ac[j] * 16,
                 g_ahl + (size_t)(m0 + ar[j]) * 2048 + aoff + ac[j] * 16);
        #pragma unroll
        for (int j = 0; j < 2; ++j)
            CP16(s + B_OFF + br[j] * ROWPITCH + bc[j] * 16,
                 g_bhl + (size_t)(n0 + br[j]) * 3072 + boff + bc[j] * 16);
        CP_COMMIT();
    };

    issue(0, 0);

    #pragma unroll 1
    for (int it = 0; it < 24; ++it) {
        int buf = it & 1;
        CP_WAIT0();
        __syncthreads();
        if (it < 23) issue(it + 1, buf ^ 1);

        uint32_t ab = stg[buf] + a_ld;
        uint32_t bb = stg[buf] + b_ld;
        #pragma unroll
        for (int kk = 0; kk < 4; ++kk) {
            uint32_t A0[4], A1[4], B0[4], B1[4];
            LDM4(A0, ab + kk * 32);
            LDM4(A1, ab + 16 * ROWPITCH + kk * 32);
            LDM4(B0, bb + kk * 32);
            LDM4(B1, bb + 16 * ROWPITCH + kk * 32);
            MMA16816(acc[0][0], A0, B0[0], B0[2]);
            MMA16816(acc[0][1], A0, B0[1], B0[3]);
            MMA16816(acc[0][2], A0, B1[0], B1[2]);
            MMA16816(acc[0][3], A0, B1[1], B1[3]);
            MMA16816(acc[1][0], A1, B0[0], B0[2]);
            MMA16816(acc[1][1], A1, B0[1], B0[3]);
            MMA16816(acc[1][2], A1, B1[0], B1[2]);
            MMA16816(acc[1][3], A1, B1[1], B1[3]);
        }
    }

    // ---- epilogue: add bias, store out ----
    int r0 = m0 + wm * 32 + (lane >> 2);
    int cb = n0 + wn * 32 + (lane & 3) * 2;
    #pragma unroll
    for (int mi = 0; mi < 2; ++mi) {
        int row = r0 + mi * 16;
        #pragma unroll
        for (int nj = 0; nj < 4; ++nj) {
            int col = cb + nj * 8;
            float b0 = __ldg(bias + col);
            float b1 = __ldg(bias + col + 1);
            if (row < N)
                *(float2*)(out + (size_t)row * D + col) =
                    make_float2(acc[mi][nj][0] + b0, acc[mi][nj][1] + b1);
            if (row + 8 < N)
                *(float2*)(out + (size_t)(row + 8) * D + col) =
                    make_float2(acc[mi][nj][2] + b0, acc[mi][nj][3] + b1);
        }
    }
}

// ---------------------------------------------------------------------------
extern "C" void kernel_launch(void* const* d_in, const int* in_sizes, int n_in,
                              void* d_out, int out_size)
{
    const float* inputs  = (const float*)d_in[0];
    const int*   dia_len = (const int*)d_in[1];
    const int*   qmask   = (const int*)d_in[2];
    const float* Wm      = (const float*)d_in[3];
    const float* bias    = (const float*)d_in[4];
    float*       out     = (float*)d_out;

    int N  = in_sizes[0] / D;      // 6000
    int nd = in_sizes[1];
    if (nd > N) nd = N;

    static bool attr_done = false;
    if (!attr_done) {
        cudaFuncSetAttribute(gemm_mma, cudaFuncAttributeMaxDynamicSharedMemorySize,
                             SMEM_TOTAL);
        attr_done = true;
    }

    prep_kernel<<<nd, 128>>>(dia_len, qmask, nd, N);
    wt_kernel<<<(N + 7) / 8, 256>>>(inputs, N);
    split_kernel<<<N + 512, 128>>>(inputs, Wm, N);

    dim3 grid((N + 127) / 128, D / 64);
    gemm_mma<<<grid, 256, SMEM_TOTAL>>>(bias, out, N);
}